// round 13
// baseline (speedup 1.0000x reference)
#include <cuda_runtime.h>
#include <math.h>

#define NB    64
#define CCH   256
#define HW    2816     // 64*44 per channel
#define WW    44
#define PPX   176
#define TOPKK 22
#define TEMP_INV 8.0f
#define GATE_THR 0.05f
#define THREADS 352    // 11 warps: one per float4 column block
#define NUNITS 108     // 22 smap + 64 token + 22 pmap
#define NSTAGE 4
#define STCH   8       // channels per stage
#define NITER  (CCH/STCH)   // 32
#define XR     180     // padded channel stride within slot
#define SLOTF  (STCH*XR)

#define TOK_ELEMS   (NB*CCH*64)
#define PRES_ELEMS  (NB*64)
#define MAP_ELEMS   (NB*64*44*64)

typedef unsigned long long u64;

__device__ int g_cnt[NB];   // zero-init; self-resetting each launch

struct __align__(16) SM {
    float lbn8[CCH*8];      // normalized basis, k-duplicated pairs {x,x,y,y,z,z,w,w}
    float dotp[PPX*4];      // raw pooled projections [p][k]
    float sup[PPX*4];
    float pw[PPX*4];
    float pwT[4*PPX];
    float fe[PPX];
    float nrm[PPX];
    float red[32];
    float scal[16];
    int   ctr;
    int   flag;
};

#define SMEM_TOTAL ((int)(sizeof(SM) + NSTAGE*SLOTF*sizeof(float)))

__device__ __forceinline__ float wsum(float v) {
#pragma unroll
    for (int o = 16; o; o >>= 1) v += __shfl_xor_sync(0xffffffffu, v, o);
    return v;
}
__device__ __forceinline__ float wmaxr(float v) {
#pragma unroll
    for (int o = 16; o; o >>= 1) v = fmaxf(v, __shfl_xor_sync(0xffffffffu, v, o));
    return v;
}
__device__ __forceinline__ u64 pk2(float lo, float hi) {
    u64 r; asm("mov.b64 %0,{%1,%2};" : "=l"(r) : "f"(lo), "f"(hi)); return r;
}
__device__ __forceinline__ void up2(u64 v, float& a, float& b) {
    asm("mov.b64 {%0,%1},%2;" : "=f"(a), "=f"(b) : "l"(v));
}
__device__ __forceinline__ u64 ffma2(u64 a, u64 b, u64 c) {
    u64 d; asm("fma.rn.f32x2 %0,%1,%2,%3;" : "=l"(d) : "l"(a), "l"(b), "l"(c)); return d;
}
__device__ __forceinline__ u64 fadd2(u64 a, u64 b) {
    u64 d; asm("add.rn.f32x2 %0,%1,%2;" : "=l"(d) : "l"(a), "l"(b)); return d;
}
__device__ __forceinline__ void fill_stage(float* slot, const float* xb, int c0, int tid) {
    int ch = tid / 44, q = tid - 44 * ch;        // tid < 352 exactly covers 8ch x 44 float4
    const float* src = xb + (size_t)(c0 + ch) * HW + q * 4;
    unsigned daddr = (unsigned)__cvta_generic_to_shared(slot + ch * XR + q * 4);
    asm volatile("cp.async.cg.shared.global [%0],[%1],16;" :: "r"(daddr), "l"(src));
}

__global__ void __launch_bounds__(THREADS, 4)
fused_stripe_kernel(const float* __restrict__ x, const float* __restrict__ lb,
                    float* __restrict__ out_tok, float* __restrict__ out_pres,
                    float* __restrict__ out_smap, float* __restrict__ out_pmap)
{
    extern __shared__ char smraw[];
    SM& s = *reinterpret_cast<SM*>(smraw);
    float* ring = reinterpret_cast<float*>(smraw + sizeof(SM));
    const unsigned FULL = 0xffffffffu;
    const int tid = threadIdx.x, lane = tid & 31, wid = tid >> 5;
    const int blk = blockIdx.x;
    const int n = blk >> 4, g = blk & 15;
    const float* xb = x + (size_t)n * (CCH * HW) + (size_t)g * PPX;

    // ---------- Prologue: kick off first 3 stage fills ----------
#pragma unroll
    for (int ss = 0; ss < 3; ++ss) {
        fill_stage(ring + ss * SLOTF, xb, ss * STCH, tid);
        asm volatile("cp.async.commit_group;");
    }

    // ---------- Phase 1: load + L2-normalize latent basis ----------
    {
        if (tid == 0) { s.ctr = 0; s.flag = 0; }
        float v0 = 0, v1 = 0, v2 = 0, v3 = 0;
        if (tid < 256) {
            const float* lbg = lb + (size_t)g * (4 * CCH);
            v0 = lbg[tid]; v1 = lbg[CCH + tid]; v2 = lbg[2 * CCH + tid]; v3 = lbg[3 * CCH + tid];
            float s0 = wsum(v0 * v0), s1 = wsum(v1 * v1), s2 = wsum(v2 * v2), s3 = wsum(v3 * v3);
            if (lane == 0) { s.red[wid] = s0; s.red[8 + wid] = s1; s.red[16 + wid] = s2; s.red[24 + wid] = s3; }
        }
        __syncthreads();
        if (tid < 4) {
            float ss = 0.f;
#pragma unroll
            for (int j = 0; j < 8; ++j) ss += s.red[tid * 8 + j];
            s.scal[tid] = 1.0f / fmaxf(sqrtf(ss), 1e-12f);
        }
        __syncthreads();
        if (tid < 256) {
            float ox = v0 * s.scal[0], oy = v1 * s.scal[1], oz = v2 * s.scal[2], ow = v3 * s.scal[3];
            *reinterpret_cast<float4*>(&s.lbn8[tid * 8 + 0]) = make_float4(ox, ox, oy, oy);
            *reinterpret_cast<float4*>(&s.lbn8[tid * 8 + 4]) = make_float4(oz, oz, ow, ow);
        }
    }

    // ---------- Phase 2: (channel x row) layout, all stencil taps via LDS ----------
    {
        const int w = wid;                 // colblock 0..10
        const int c8 = lane >> 2, r = lane & 3;
        const int ru = (r > 0) ? r - 1 : 0, rd = (r < 3) ? r + 1 : 3;
        const float fu = (r > 0) ? 1.f : 0.f, fd = (r < 3) ? 1.f : 0.f;
        const u64 fu2 = pk2(fu, fu), fd2 = pk2(fd, fd);
        const bool haslw = (w > 0), hasrw = (w < 10);
        const int xoff  = c8 * XR + r  * WW + w * 4;
        const int xoffu = c8 * XR + ru * WW + w * 4;
        const int xoffd = c8 * XR + rd * WW + w * 4;

        u64 pd0a = 0, pd0b = 0, pd1a = 0, pd1b = 0, pd2a = 0, pd2b = 0, pd3a = 0, pd3b = 0;
        u64 fea = 0, feb = 0, nra = 0, nrb = 0;

#pragma unroll 1
        for (int it = 0; it < NITER; ++it) {
            asm volatile("cp.async.wait_group 2;");
            __syncthreads();
            if (it + 3 < NITER)
                fill_stage(ring + ((it + 3) & (NSTAGE - 1)) * SLOTF, xb, (it + 3) * STCH, tid);
            asm volatile("cp.async.commit_group;");

            const float* st = ring + (it & (NSTAGE - 1)) * SLOTF;
            ulonglong2 xm = *reinterpret_cast<const ulonglong2*>(st + xoff);
            ulonglong2 xu = *reinterpret_cast<const ulonglong2*>(st + xoffu);
            ulonglong2 xd = *reinterpret_cast<const ulonglong2*>(st + xoffd);
            float ml = haslw ? st[xoff - 1]  : 0.f;
            float ul = haslw ? st[xoffu - 1] : 0.f;
            float dl = haslw ? st[xoffd - 1] : 0.f;
            float mr = hasrw ? st[xoff + 4]  : 0.f;
            float ur = hasrw ? st[xoffu + 4] : 0.f;
            float dr = hasrw ? st[xoffd + 4] : 0.f;

            u64 vs01 = ffma2(xu.x, fu2, ffma2(xd.x, fd2, xm.x));
            u64 vs23 = ffma2(xu.y, fu2, ffma2(xd.y, fd2, xm.y));
            float vlw = fmaf(fu, ul, fmaf(fd, dl, ml));
            float vrw = fmaf(fu, ur, fmaf(fd, dr, mr));
            float v0, v1, v2, v3;
            up2(vs01, v0, v1); up2(vs23, v2, v3);
            u64 pl01 = pk2(vlw + v0 + v1, v0 + v1 + v2);
            u64 pl23 = pk2(v1 + v2 + v3, v2 + v3 + vrw);

            const ulonglong2* lb8 = reinterpret_cast<const ulonglong2*>(&s.lbn8[(it * STCH + c8) * 8]);
            ulonglong2 lxy = lb8[0], lzw = lb8[1];
            pd0a = ffma2(pl01, lxy.x, pd0a); pd0b = ffma2(pl23, lxy.x, pd0b);
            pd1a = ffma2(pl01, lxy.y, pd1a); pd1b = ffma2(pl23, lxy.y, pd1b);
            pd2a = ffma2(pl01, lzw.x, pd2a); pd2b = ffma2(pl23, lzw.x, pd2b);
            pd3a = ffma2(pl01, lzw.y, pd3a); pd3b = ffma2(pl23, lzw.y, pd3b);
            fea = ffma2(xm.x, xm.x, fea);    feb = ffma2(xm.y, xm.y, feb);
            nra = ffma2(pl01, pl01, nra);    nrb = ffma2(pl23, pl23, nrb);
        }

        // cross-c8 reduction (lanes with equal r, strides 4/8/16)
#pragma unroll
        for (int off = 4; off <= 16; off <<= 1) {
            pd0a = fadd2(pd0a, __shfl_xor_sync(FULL, pd0a, off));
            pd0b = fadd2(pd0b, __shfl_xor_sync(FULL, pd0b, off));
            pd1a = fadd2(pd1a, __shfl_xor_sync(FULL, pd1a, off));
            pd1b = fadd2(pd1b, __shfl_xor_sync(FULL, pd1b, off));
            pd2a = fadd2(pd2a, __shfl_xor_sync(FULL, pd2a, off));
            pd2b = fadd2(pd2b, __shfl_xor_sync(FULL, pd2b, off));
            pd3a = fadd2(pd3a, __shfl_xor_sync(FULL, pd3a, off));
            pd3b = fadd2(pd3b, __shfl_xor_sync(FULL, pd3b, off));
            fea  = fadd2(fea,  __shfl_xor_sync(FULL, fea,  off));
            feb  = fadd2(feb,  __shfl_xor_sync(FULL, feb,  off));
            nra  = fadd2(nra,  __shfl_xor_sync(FULL, nra,  off));
            nrb  = fadd2(nrb,  __shfl_xor_sync(FULL, nrb,  off));
        }
        if (lane < 4) {
            const int po = lane * WW + w * 4;    // 4-aligned (44 % 4 == 0)
            float k0p0,k0p1,k0p2,k0p3, k1p0,k1p1,k1p2,k1p3;
            float k2p0,k2p1,k2p2,k2p3, k3p0,k3p1,k3p2,k3p3;
            up2(pd0a,k0p0,k0p1); up2(pd0b,k0p2,k0p3);
            up2(pd1a,k1p0,k1p1); up2(pd1b,k1p2,k1p3);
            up2(pd2a,k2p0,k2p1); up2(pd2b,k2p2,k2p3);
            up2(pd3a,k3p0,k3p1); up2(pd3b,k3p2,k3p3);
            float f0,f1,f2,f3, n0,n1,n2,n3;
            up2(fea,f0,f1); up2(feb,f2,f3);
            up2(nra,n0,n1); up2(nrb,n2,n3);
            *reinterpret_cast<float4*>(&s.dotp[(po+0)*4]) = make_float4(k0p0,k1p0,k2p0,k3p0);
            *reinterpret_cast<float4*>(&s.dotp[(po+1)*4]) = make_float4(k0p1,k1p1,k2p1,k3p1);
            *reinterpret_cast<float4*>(&s.dotp[(po+2)*4]) = make_float4(k0p2,k1p2,k2p2,k3p2);
            *reinterpret_cast<float4*>(&s.dotp[(po+3)*4]) = make_float4(k0p3,k1p3,k2p3,k3p3);
            *reinterpret_cast<float4*>(&s.fe[po])  = make_float4(f0*(1.f/CCH), f1*(1.f/CCH),
                                                                 f2*(1.f/CCH), f3*(1.f/CCH));
            *reinterpret_cast<float4*>(&s.nrm[po]) = make_float4(n0, n1, n2, n3);
        }
    }
    __syncthreads();

    // ---------- Phase 3: fe max + active count ----------
    float fev = 0.f, nmv = 0.f;
    float4 dtv = make_float4(0.f, 0.f, 0.f, 0.f);
    if (tid < PPX) {
        fev = s.fe[tid]; nmv = s.nrm[tid];
        dtv = *reinterpret_cast<float4*>(&s.dotp[tid * 4]);
    }
    {
        float m = wmaxr((tid < PPX) ? fev : 0.f);
        if (lane == 0) s.red[wid] = m;
    }
    __syncthreads();
    float invmax;
    {
        float mm = s.red[0];
#pragma unroll
        for (int j = 1; j < 11; ++j) mm = fmaxf(mm, s.red[j]);
        invmax = 1.0f / fmaxf(mm, 1e-6f);
    }
    int pred = (tid < PPX) && (fev * invmax > GATE_THR);
    int cnt = __syncthreads_count(pred);

    // ---------- Phase 4: softmax routing -> support (1/9 & 1/81 cancel) ----------
    if (tid < PPX) {
        float sc = TEMP_INV / fmaxf(sqrtf(nmv), 9e-12f);
        float l0 = dtv.x * sc, l1 = dtv.y * sc, l2 = dtv.z * sc, l3 = dtv.w * sc;
        float m = fmaxf(fmaxf(l0, l1), fmaxf(l2, l3));
        float e0 = __expf(l0 - m), e1 = __expf(l1 - m), e2 = __expf(l2 - m), e3 = __expf(l3 - m);
        float inv = 1.0f / (e0 + e1 + e2 + e3);
        float fes = fev * invmax;
        float act = (cnt > 0) ? (fes > GATE_THR ? 1.f : 0.f) : (fes > 0.f ? 1.f : 0.f);
        float w_ = inv * act;
        *reinterpret_cast<float4*>(&s.sup[tid * 4]) = make_float4(e0 * w_, e1 * w_, e2 * w_, e3 * w_);
    }
    __syncthreads();

    // ---------- Phase 5: overlapped tail ----------
    float* smb = out_smap + (size_t)n * (HW * 64) + (size_t)g * (PPX * 64);
    float* pmb = out_pmap + (size_t)n * (HW * 64) + (size_t)g * (PPX * 64);

    if (wid == 0) {
        float s0 = 0, s1 = 0, s2 = 0, s3 = 0;
        for (int pp = lane; pp < PPX; pp += 32) {
            float4 v = *reinterpret_cast<float4*>(&s.sup[pp * 4]);
            s0 += v.x; s1 += v.y; s2 += v.z; s3 += v.w;
        }
        s0 = wsum(s0); s1 = wsum(s1); s2 = wsum(s2); s3 = wsum(s3);
        float i0 = 1.0f / fmaxf(s0, 1e-6f), i1 = 1.0f / fmaxf(s1, 1e-6f);
        float i2 = 1.0f / fmaxf(s2, 1e-6f), i3 = 1.0f / fmaxf(s3, 1e-6f);
        for (int pp = lane; pp < PPX; pp += 32) {
            float4 v = *reinterpret_cast<float4*>(&s.sup[pp * 4]);
            float4 w = make_float4(v.x * i0, v.y * i1, v.z * i2, v.w * i3);
            *reinterpret_cast<float4*>(&s.pw[pp * 4]) = w;
            s.pwT[0 * PPX + pp] = w.x;
            s.pwT[1 * PPX + pp] = w.y;
            s.pwT[2 * PPX + pp] = w.z;
            s.pwT[3 * PPX + pp] = w.w;
        }
        __threadfence_block();
        if (lane == 0) s.flag = 1;
    } else if (wid >= 4 && wid < 8) {
        const int k = wid - 4;
        float v[6];
#pragma unroll
        for (int j = 0; j < 6; ++j) {
            int pp = lane + 32 * j;
            v[j] = (pp < PPX) ? s.sup[pp * 4 + k] : -1.0f;
        }
        float sum = 0.f;
        for (int it = 0; it < TOPKK; ++it) {
            float lm = v[0]; int li = 0;
#pragma unroll
            for (int j = 1; j < 6; ++j) { if (v[j] > lm) { lm = v[j]; li = j; } }
            float wm = wmaxr(lm);
            unsigned msk = __ballot_sync(FULL, lm == wm);
            int src = __ffs(msk) - 1;
            if (lane == src) v[li] = -1.0f;
            sum += wm;
        }
        if (lane == 0) {
            out_pres[n * 64 + g * 4 + k] = sum * (1.0f / TOPKK);
            __threadfence();
        }
    }

    // work queue: units [0,22)=smap, [22,86)=tokens, [86,108)=pmap
    {
        const float4 z4 = make_float4(0.f, 0.f, 0.f, 0.f);
        bool pwReady = false;
        for (;;) {
            int u;
            if (lane == 0) u = atomicAdd(&s.ctr, 1);
            u = __shfl_sync(FULL, u, 0);
            if (u >= NUNITS) break;
            if (u >= 22 && !pwReady) {
                while (*((volatile int*)&s.flag) == 0) {}
                __threadfence_block();
                pwReady = true;
            }
            if (u < 22) {
                int base = u * 128;
#pragma unroll
                for (int j = 0; j < 4; ++j) {
                    int idx = base + j * 32 + lane;
                    int pp = idx >> 4, qd = idx & 15;
                    float4 sv = (qd == g) ? *reinterpret_cast<float4*>(&s.sup[pp * 4]) : z4;
                    *reinterpret_cast<float4*>(smb + (size_t)idx * 4) = sv;
                }
            } else if (u < 86) {
                const int grp = lane >> 3, gl = lane & 7;
                const int c = (u - 22) * 4 + grp;
                const float* xc = xb + (size_t)c * HW;
                u64 a0 = 0, a1 = 0, a2 = 0, a3 = 0;
#pragma unroll
                for (int it = 0; it < 6; ++it) {
                    int p0 = it * 32 + gl * 4;
                    if (p0 < PPX) {
                        ulonglong2 xv = *reinterpret_cast<const ulonglong2*>(xc + p0);
                        ulonglong2 w0 = *reinterpret_cast<const ulonglong2*>(&s.pwT[0 * PPX + p0]);
                        ulonglong2 w1 = *reinterpret_cast<const ulonglong2*>(&s.pwT[1 * PPX + p0]);
                        ulonglong2 w2 = *reinterpret_cast<const ulonglong2*>(&s.pwT[2 * PPX + p0]);
                        ulonglong2 w3 = *reinterpret_cast<const ulonglong2*>(&s.pwT[3 * PPX + p0]);
                        a0 = ffma2(xv.y, w0.y, ffma2(xv.x, w0.x, a0));
                        a1 = ffma2(xv.y, w1.y, ffma2(xv.x, w1.x, a1));
                        a2 = ffma2(xv.y, w2.y, ffma2(xv.x, w2.x, a2));
                        a3 = ffma2(xv.y, w3.y, ffma2(xv.x, w3.x, a3));
                    }
                }
                float x0, y0, x1, y1, x2, y2, x3, y3;
                up2(a0, x0, y0); up2(a1, x1, y1); up2(a2, x2, y2); up2(a3, x3, y3);
                float f0 = x0 + y0, f1 = x1 + y1, f2 = x2 + y2, f3 = x3 + y3;
#pragma unroll
                for (int m = 1; m <= 4; m <<= 1) {
                    f0 += __shfl_xor_sync(FULL, f0, m);
                    f1 += __shfl_xor_sync(FULL, f1, m);
                    f2 += __shfl_xor_sync(FULL, f2, m);
                    f3 += __shfl_xor_sync(FULL, f3, m);
                }
                if (gl == 0)
                    *reinterpret_cast<float4*>(out_tok + ((size_t)(n * CCH + c) * 64 + g * 4)) =
                        make_float4(f0, f1, f2, f3);
            } else {
                int base = (u - 86) * 128;
#pragma unroll
                for (int j = 0; j < 4; ++j) {
                    int idx = base + j * 32 + lane;
                    int pp = idx >> 4, qd = idx & 15;
                    float4 pv = (qd == g) ? *reinterpret_cast<float4*>(&s.pw[pp * 4]) : z4;
                    *reinterpret_cast<float4*>(pmb + (size_t)idx * 4) = pv;
                }
            }
        }
    }

    // ---------- Phase 9: last CTA of batch n normalizes presence ----------
    __syncthreads();
    if (tid == 0) {
        __threadfence();
        int old = atomicAdd(&g_cnt[n], 1);
        s.red[0] = (old == 15) ? 1.f : 0.f;
    }
    __syncthreads();
    if (s.red[0] != 0.f && wid == 0) {
        __threadfence();
        float a = out_pres[n * 64 + lane];
        float b = out_pres[n * 64 + 32 + lane];
        float t = wsum(a + b);
        float inv = 1.0f / fmaxf(t, 1e-6f);
        out_pres[n * 64 + lane] = a * inv;
        out_pres[n * 64 + 32 + lane] = b * inv;
        if (lane == 0) g_cnt[n] = 0;
    }
}

extern "C" void kernel_launch(void* const* d_in, const int* in_sizes, int n_in,
                              void* d_out, int out_size)
{
    const float* x  = (const float*)d_in[0];
    const float* lb = (const float*)d_in[1];
    float* out = (float*)d_out;

    float* tok  = out;
    float* pres = out + TOK_ELEMS;
    float* smap = out + TOK_ELEMS + PRES_ELEMS;
    float* pmap = out + TOK_ELEMS + PRES_ELEMS + MAP_ELEMS;

    cudaFuncSetAttribute(fused_stripe_kernel,
                         cudaFuncAttributeMaxDynamicSharedMemorySize, SMEM_TOTAL);
    fused_stripe_kernel<<<NB * 16, THREADS, SMEM_TOTAL>>>(x, lb, tok, pres, smap, pmap);
}

// round 14
// speedup vs baseline: 1.3181x; 1.3181x over previous
#include <cuda_runtime.h>
#include <math.h>

#define NB    64
#define CCH   256
#define HW    2816     // 64*44 per channel
#define WW    44
#define PPX   176
#define TOPKK 22
#define TEMP_INV 8.0f
#define GATE_THR 0.05f
#define THREADS 352    // 11 warps: one per float4 column block
#define NUNITS 108     // 22 smap + 64 token + 22 pmap
#define NSTAGE 4
#define STCH   8       // channels per stage
#define NITER  (CCH/STCH)   // 32
#define XR     180     // padded channel stride within slot
#define SLOTF  (STCH*XR)

#define TOK_ELEMS   (NB*CCH*64)
#define PRES_ELEMS  (NB*64)
#define MAP_ELEMS   (NB*64*44*64)

typedef unsigned long long u64;

__device__ int g_cnt[NB];   // zero-init; self-resetting each launch

struct __align__(16) SM {
    float lbn8[CCH*8];      // normalized basis, k-duplicated pairs {x,x,y,y,z,z,w,w}
    float dotp[PPX*4];      // raw pooled projections [p][k]
    float sup[PPX*4];
    float pw[PPX*4];
    float pwT[4*PPX];
    float fe[PPX];
    float nrm[PPX];
    float red[32];
    float scal[16];
    int   ctr;
    int   flag;
};

#define SMEM_TOTAL ((int)(sizeof(SM) + NSTAGE*SLOTF*sizeof(float)))

__device__ __forceinline__ float wsum(float v) {
#pragma unroll
    for (int o = 16; o; o >>= 1) v += __shfl_xor_sync(0xffffffffu, v, o);
    return v;
}
__device__ __forceinline__ float wmaxr(float v) {
#pragma unroll
    for (int o = 16; o; o >>= 1) v = fmaxf(v, __shfl_xor_sync(0xffffffffu, v, o));
    return v;
}
__device__ __forceinline__ u64 pk2(float lo, float hi) {
    u64 r; asm("mov.b64 %0,{%1,%2};" : "=l"(r) : "f"(lo), "f"(hi)); return r;
}
__device__ __forceinline__ void up2(u64 v, float& a, float& b) {
    asm("mov.b64 {%0,%1},%2;" : "=f"(a), "=f"(b) : "l"(v));
}
__device__ __forceinline__ u64 ffma2(u64 a, u64 b, u64 c) {
    u64 d; asm("fma.rn.f32x2 %0,%1,%2,%3;" : "=l"(d) : "l"(a), "l"(b), "l"(c)); return d;
}
__device__ __forceinline__ u64 fadd2(u64 a, u64 b) {
    u64 d; asm("add.rn.f32x2 %0,%1,%2;" : "=l"(d) : "l"(a), "l"(b)); return d;
}
__device__ __forceinline__ void fill_stage(float* slot, const float* xb, int c0, int tid) {
    int ch = tid / 44, q = tid - 44 * ch;        // tid < 352 exactly covers 8ch x 44 float4
    const float* src = xb + (size_t)(c0 + ch) * HW + q * 4;
    unsigned daddr = (unsigned)__cvta_generic_to_shared(slot + ch * XR + q * 4);
    asm volatile("cp.async.cg.shared.global [%0],[%1],16;" :: "r"(daddr), "l"(src));
}

__global__ void __launch_bounds__(THREADS, 4)
fused_stripe_kernel(const float* __restrict__ x, const float* __restrict__ lb,
                    float* __restrict__ out_tok, float* __restrict__ out_pres,
                    float* __restrict__ out_smap, float* __restrict__ out_pmap)
{
    extern __shared__ char smraw[];
    SM& s = *reinterpret_cast<SM*>(smraw);
    float* ring = reinterpret_cast<float*>(smraw + sizeof(SM));
    const unsigned FULL = 0xffffffffu;
    const int tid = threadIdx.x, lane = tid & 31, wid = tid >> 5;
    const int blk = blockIdx.x;
    const int n = blk >> 4, g = blk & 15;
    const float* xb = x + (size_t)n * (CCH * HW) + (size_t)g * PPX;

    // ---------- Prologue: kick off first 3 stage fills ----------
#pragma unroll
    for (int ss = 0; ss < 3; ++ss) {
        fill_stage(ring + ss * SLOTF, xb, ss * STCH, tid);
        asm volatile("cp.async.commit_group;");
    }

    // ---------- Phase 1: load + L2-normalize latent basis ----------
    {
        if (tid == 0) { s.ctr = 0; s.flag = 0; }
        float v0 = 0, v1 = 0, v2 = 0, v3 = 0;
        if (tid < 256) {
            const float* lbg = lb + (size_t)g * (4 * CCH);
            v0 = lbg[tid]; v1 = lbg[CCH + tid]; v2 = lbg[2 * CCH + tid]; v3 = lbg[3 * CCH + tid];
            float s0 = wsum(v0 * v0), s1 = wsum(v1 * v1), s2 = wsum(v2 * v2), s3 = wsum(v3 * v3);
            if (lane == 0) { s.red[wid] = s0; s.red[8 + wid] = s1; s.red[16 + wid] = s2; s.red[24 + wid] = s3; }
        }
        __syncthreads();
        if (tid < 4) {
            float ss = 0.f;
#pragma unroll
            for (int j = 0; j < 8; ++j) ss += s.red[tid * 8 + j];
            s.scal[tid] = 1.0f / fmaxf(sqrtf(ss), 1e-12f);
        }
        __syncthreads();
        if (tid < 256) {
            float ox = v0 * s.scal[0], oy = v1 * s.scal[1], oz = v2 * s.scal[2], ow = v3 * s.scal[3];
            *reinterpret_cast<float4*>(&s.lbn8[tid * 8 + 0]) = make_float4(ox, ox, oy, oy);
            *reinterpret_cast<float4*>(&s.lbn8[tid * 8 + 4]) = make_float4(oz, oz, ow, ow);
        }
    }

    // ---------- Phase 2: (channel x row) lane layout, shfl vertical stencil ----------
    {
        const int w = wid;                 // colblock 0..10
        const int c8 = lane >> 2, r = lane & 3;
        const float fu = (r > 0) ? 1.f : 0.f, fd = (r < 3) ? 1.f : 0.f;
        const bool haslw = (w > 0), hasrw = (w < 10);
        const int xoff = c8 * XR + r * WW + w * 4;

        u64 pd0a = 0, pd0b = 0, pd1a = 0, pd1b = 0, pd2a = 0, pd2b = 0, pd3a = 0, pd3b = 0;
        u64 fea = 0, feb = 0, nra = 0, nrb = 0;

#pragma unroll 1
        for (int it = 0; it < NITER; ++it) {
            asm volatile("cp.async.wait_group 2;");
            __syncthreads();
            if (it + 3 < NITER)
                fill_stage(ring + ((it + 3) & (NSTAGE - 1)) * SLOTF, xb, (it + 3) * STCH, tid);
            asm volatile("cp.async.commit_group;");

            const float* st = ring + (it & (NSTAGE - 1)) * SLOTF;
            ulonglong2 xm = *reinterpret_cast<const ulonglong2*>(st + xoff);
            float lwv = haslw ? st[xoff - 1] : 0.f;
            float rwv = hasrw ? st[xoff + 4] : 0.f;

            float m0, m1, m2, m3;
            up2(xm.x, m0, m1); up2(xm.y, m2, m3);
            float v0 = fmaf(fu, __shfl_up_sync(FULL, m0, 1), fmaf(fd, __shfl_down_sync(FULL, m0, 1), m0));
            float v1 = fmaf(fu, __shfl_up_sync(FULL, m1, 1), fmaf(fd, __shfl_down_sync(FULL, m1, 1), m1));
            float v2 = fmaf(fu, __shfl_up_sync(FULL, m2, 1), fmaf(fd, __shfl_down_sync(FULL, m2, 1), m2));
            float v3 = fmaf(fu, __shfl_up_sync(FULL, m3, 1), fmaf(fd, __shfl_down_sync(FULL, m3, 1), m3));
            float vlw = fmaf(fu, __shfl_up_sync(FULL, lwv, 1), fmaf(fd, __shfl_down_sync(FULL, lwv, 1), lwv));
            float vrw = fmaf(fu, __shfl_up_sync(FULL, rwv, 1), fmaf(fd, __shfl_down_sync(FULL, rwv, 1), rwv));

            u64 pl01 = pk2(vlw + v0 + v1, v0 + v1 + v2);
            u64 pl23 = pk2(v1 + v2 + v3, v2 + v3 + vrw);

            const ulonglong2* lb8 = reinterpret_cast<const ulonglong2*>(&s.lbn8[(it * STCH + c8) * 8]);
            ulonglong2 lxy = lb8[0], lzw = lb8[1];
            pd0a = ffma2(pl01, lxy.x, pd0a); pd0b = ffma2(pl23, lxy.x, pd0b);
            pd1a = ffma2(pl01, lxy.y, pd1a); pd1b = ffma2(pl23, lxy.y, pd1b);
            pd2a = ffma2(pl01, lzw.x, pd2a); pd2b = ffma2(pl23, lzw.x, pd2b);
            pd3a = ffma2(pl01, lzw.y, pd3a); pd3b = ffma2(pl23, lzw.y, pd3b);
            fea = ffma2(xm.x, xm.x, fea);    feb = ffma2(xm.y, xm.y, feb);
            nra = ffma2(pl01, pl01, nra);    nrb = ffma2(pl23, pl23, nrb);
        }

        // cross-c8 reduction (lanes with equal r, strides 4/8/16)
#pragma unroll
        for (int off = 4; off <= 16; off <<= 1) {
            pd0a = fadd2(pd0a, __shfl_xor_sync(FULL, pd0a, off));
            pd0b = fadd2(pd0b, __shfl_xor_sync(FULL, pd0b, off));
            pd1a = fadd2(pd1a, __shfl_xor_sync(FULL, pd1a, off));
            pd1b = fadd2(pd1b, __shfl_xor_sync(FULL, pd1b, off));
            pd2a = fadd2(pd2a, __shfl_xor_sync(FULL, pd2a, off));
            pd2b = fadd2(pd2b, __shfl_xor_sync(FULL, pd2b, off));
            pd3a = fadd2(pd3a, __shfl_xor_sync(FULL, pd3a, off));
            pd3b = fadd2(pd3b, __shfl_xor_sync(FULL, pd3b, off));
            fea  = fadd2(fea,  __shfl_xor_sync(FULL, fea,  off));
            feb  = fadd2(feb,  __shfl_xor_sync(FULL, feb,  off));
            nra  = fadd2(nra,  __shfl_xor_sync(FULL, nra,  off));
            nrb  = fadd2(nrb,  __shfl_xor_sync(FULL, nrb,  off));
        }
        if (lane < 4) {
            const int po = lane * WW + w * 4;    // 4-aligned (44 % 4 == 0)
            float k0p0,k0p1,k0p2,k0p3, k1p0,k1p1,k1p2,k1p3;
            float k2p0,k2p1,k2p2,k2p3, k3p0,k3p1,k3p2,k3p3;
            up2(pd0a,k0p0,k0p1); up2(pd0b,k0p2,k0p3);
            up2(pd1a,k1p0,k1p1); up2(pd1b,k1p2,k1p3);
            up2(pd2a,k2p0,k2p1); up2(pd2b,k2p2,k2p3);
            up2(pd3a,k3p0,k3p1); up2(pd3b,k3p2,k3p3);
            float f0,f1,f2,f3, n0,n1,n2,n3;
            up2(fea,f0,f1); up2(feb,f2,f3);
            up2(nra,n0,n1); up2(nrb,n2,n3);
            *reinterpret_cast<float4*>(&s.dotp[(po+0)*4]) = make_float4(k0p0,k1p0,k2p0,k3p0);
            *reinterpret_cast<float4*>(&s.dotp[(po+1)*4]) = make_float4(k0p1,k1p1,k2p1,k3p1);
            *reinterpret_cast<float4*>(&s.dotp[(po+2)*4]) = make_float4(k0p2,k1p2,k2p2,k3p2);
            *reinterpret_cast<float4*>(&s.dotp[(po+3)*4]) = make_float4(k0p3,k1p3,k2p3,k3p3);
            *reinterpret_cast<float4*>(&s.fe[po])  = make_float4(f0*(1.f/CCH), f1*(1.f/CCH),
                                                                 f2*(1.f/CCH), f3*(1.f/CCH));
            *reinterpret_cast<float4*>(&s.nrm[po]) = make_float4(n0, n1, n2, n3);
        }
    }
    __syncthreads();

    // ---------- Phase 3: fe max + active count ----------
    float fev = 0.f, nmv = 0.f;
    float4 dtv = make_float4(0.f, 0.f, 0.f, 0.f);
    if (tid < PPX) {
        fev = s.fe[tid]; nmv = s.nrm[tid];
        dtv = *reinterpret_cast<float4*>(&s.dotp[tid * 4]);
    }
    {
        float m = wmaxr((tid < PPX) ? fev : 0.f);
        if (lane == 0) s.red[wid] = m;
    }
    __syncthreads();
    float invmax;
    {
        float mm = s.red[0];
#pragma unroll
        for (int j = 1; j < 11; ++j) mm = fmaxf(mm, s.red[j]);
        invmax = 1.0f / fmaxf(mm, 1e-6f);
    }
    int pred = (tid < PPX) && (fev * invmax > GATE_THR);
    int cnt = __syncthreads_count(pred);

    // ---------- Phase 4: softmax routing -> support (1/9 & 1/81 cancel) ----------
    if (tid < PPX) {
        float sc = TEMP_INV / fmaxf(sqrtf(nmv), 9e-12f);
        float l0 = dtv.x * sc, l1 = dtv.y * sc, l2 = dtv.z * sc, l3 = dtv.w * sc;
        float m = fmaxf(fmaxf(l0, l1), fmaxf(l2, l3));
        float e0 = __expf(l0 - m), e1 = __expf(l1 - m), e2 = __expf(l2 - m), e3 = __expf(l3 - m);
        float inv = 1.0f / (e0 + e1 + e2 + e3);
        float fes = fev * invmax;
        float act = (cnt > 0) ? (fes > GATE_THR ? 1.f : 0.f) : (fes > 0.f ? 1.f : 0.f);
        float w_ = inv * act;
        *reinterpret_cast<float4*>(&s.sup[tid * 4]) = make_float4(e0 * w_, e1 * w_, e2 * w_, e3 * w_);
    }
    __syncthreads();

    // ---------- Phase 5: overlapped tail ----------
    float* smb = out_smap + (size_t)n * (HW * 64) + (size_t)g * (PPX * 64);
    float* pmb = out_pmap + (size_t)n * (HW * 64) + (size_t)g * (PPX * 64);

    if (wid == 0) {
        float s0 = 0, s1 = 0, s2 = 0, s3 = 0;
        for (int pp = lane; pp < PPX; pp += 32) {
            float4 v = *reinterpret_cast<float4*>(&s.sup[pp * 4]);
            s0 += v.x; s1 += v.y; s2 += v.z; s3 += v.w;
        }
        s0 = wsum(s0); s1 = wsum(s1); s2 = wsum(s2); s3 = wsum(s3);
        float i0 = 1.0f / fmaxf(s0, 1e-6f), i1 = 1.0f / fmaxf(s1, 1e-6f);
        float i2 = 1.0f / fmaxf(s2, 1e-6f), i3 = 1.0f / fmaxf(s3, 1e-6f);
        for (int pp = lane; pp < PPX; pp += 32) {
            float4 v = *reinterpret_cast<float4*>(&s.sup[pp * 4]);
            float4 w = make_float4(v.x * i0, v.y * i1, v.z * i2, v.w * i3);
            *reinterpret_cast<float4*>(&s.pw[pp * 4]) = w;
            s.pwT[0 * PPX + pp] = w.x;
            s.pwT[1 * PPX + pp] = w.y;
            s.pwT[2 * PPX + pp] = w.z;
            s.pwT[3 * PPX + pp] = w.w;
        }
        __threadfence_block();
        if (lane == 0) s.flag = 1;
    } else if (wid >= 4 && wid < 8) {
        const int k = wid - 4;
        float v[6];
#pragma unroll
        for (int j = 0; j < 6; ++j) {
            int pp = lane + 32 * j;
            v[j] = (pp < PPX) ? s.sup[pp * 4 + k] : -1.0f;
        }
        float sum = 0.f;
        for (int it = 0; it < TOPKK; ++it) {
            float lm = v[0]; int li = 0;
#pragma unroll
            for (int j = 1; j < 6; ++j) { if (v[j] > lm) { lm = v[j]; li = j; } }
            float wm = wmaxr(lm);
            unsigned msk = __ballot_sync(FULL, lm == wm);
            int src = __ffs(msk) - 1;
            if (lane == src) v[li] = -1.0f;
            sum += wm;
        }
        if (lane == 0) {
            out_pres[n * 64 + g * 4 + k] = sum * (1.0f / TOPKK);
            __threadfence();
        }
    }

    // work queue: units [0,22)=smap, [22,86)=tokens, [86,108)=pmap
    {
        const float4 z4 = make_float4(0.f, 0.f, 0.f, 0.f);
        bool pwReady = false;
        for (;;) {
            int u;
            if (lane == 0) u = atomicAdd(&s.ctr, 1);
            u = __shfl_sync(FULL, u, 0);
            if (u >= NUNITS) break;
            if (u >= 22 && !pwReady) {
                while (*((volatile int*)&s.flag) == 0) {}
                __threadfence_block();
                pwReady = true;
            }
            if (u < 22) {
                int base = u * 128;
#pragma unroll
                for (int j = 0; j < 4; ++j) {
                    int idx = base + j * 32 + lane;
                    int pp = idx >> 4, qd = idx & 15;
                    float4 sv = (qd == g) ? *reinterpret_cast<float4*>(&s.sup[pp * 4]) : z4;
                    *reinterpret_cast<float4*>(smb + (size_t)idx * 4) = sv;
                }
            } else if (u < 86) {
                const int grp = lane >> 3, gl = lane & 7;
                const int c = (u - 22) * 4 + grp;
                const float* xc = xb + (size_t)c * HW;
                u64 a0 = 0, a1 = 0, a2 = 0, a3 = 0;
#pragma unroll
                for (int it = 0; it < 6; ++it) {
                    int p0 = it * 32 + gl * 4;
                    if (p0 < PPX) {
                        ulonglong2 xv = *reinterpret_cast<const ulonglong2*>(xc + p0);
                        ulonglong2 w0 = *reinterpret_cast<const ulonglong2*>(&s.pwT[0 * PPX + p0]);
                        ulonglong2 w1 = *reinterpret_cast<const ulonglong2*>(&s.pwT[1 * PPX + p0]);
                        ulonglong2 w2 = *reinterpret_cast<const ulonglong2*>(&s.pwT[2 * PPX + p0]);
                        ulonglong2 w3 = *reinterpret_cast<const ulonglong2*>(&s.pwT[3 * PPX + p0]);
                        a0 = ffma2(xv.y, w0.y, ffma2(xv.x, w0.x, a0));
                        a1 = ffma2(xv.y, w1.y, ffma2(xv.x, w1.x, a1));
                        a2 = ffma2(xv.y, w2.y, ffma2(xv.x, w2.x, a2));
                        a3 = ffma2(xv.y, w3.y, ffma2(xv.x, w3.x, a3));
                    }
                }
                float x0, y0, x1, y1, x2, y2, x3, y3;
                up2(a0, x0, y0); up2(a1, x1, y1); up2(a2, x2, y2); up2(a3, x3, y3);
                float f0 = x0 + y0, f1 = x1 + y1, f2 = x2 + y2, f3 = x3 + y3;
#pragma unroll
                for (int m = 1; m <= 4; m <<= 1) {
                    f0 += __shfl_xor_sync(FULL, f0, m);
                    f1 += __shfl_xor_sync(FULL, f1, m);
                    f2 += __shfl_xor_sync(FULL, f2, m);
                    f3 += __shfl_xor_sync(FULL, f3, m);
                }
                if (gl == 0)
                    *reinterpret_cast<float4*>(out_tok + ((size_t)(n * CCH + c) * 64 + g * 4)) =
                        make_float4(f0, f1, f2, f3);
            } else {
                int base = (u - 86) * 128;
#pragma unroll
                for (int j = 0; j < 4; ++j) {
                    int idx = base + j * 32 + lane;
                    int pp = idx >> 4, qd = idx & 15;
                    float4 pv = (qd == g) ? *reinterpret_cast<float4*>(&s.pw[pp * 4]) : z4;
                    *reinterpret_cast<float4*>(pmb + (size_t)idx * 4) = pv;
                }
            }
        }
    }

    // ---------- Phase 9: last CTA of batch n normalizes presence ----------
    __syncthreads();
    if (tid == 0) {
        __threadfence();
        int old = atomicAdd(&g_cnt[n], 1);
        s.red[0] = (old == 15) ? 1.f : 0.f;
    }
    __syncthreads();
    if (s.red[0] != 0.f && wid == 0) {
        __threadfence();
        float a = out_pres[n * 64 + lane];
        float b = out_pres[n * 64 + 32 + lane];
        float t = wsum(a + b);
        float inv = 1.0f / fmaxf(t, 1e-6f);
        out_pres[n * 64 + lane] = a * inv;
        out_pres[n * 64 + 32 + lane] = b * inv;
        if (lane == 0) g_cnt[n] = 0;
    }
}

extern "C" void kernel_launch(void* const* d_in, const int* in_sizes, int n_in,
                              void* d_out, int out_size)
{
    const float* x  = (const float*)d_in[0];
    const float* lb = (const float*)d_in[1];
    float* out = (float*)d_out;

    float* tok  = out;
    float* pres = out + TOK_ELEMS;
    float* smap = out + TOK_ELEMS + PRES_ELEMS;
    float* pmap = out + TOK_ELEMS + PRES_ELEMS + MAP_ELEMS;

    cudaFuncSetAttribute(fused_stripe_kernel,
                         cudaFuncAttributeMaxDynamicSharedMemorySize, SMEM_TOTAL);
    fused_stripe_kernel<<<NB * 16, THREADS, SMEM_TOTAL>>>(x, lb, tok, pres, smap, pmap);
}

// round 15
// speedup vs baseline: 1.7386x; 1.3190x over previous
#include <cuda_runtime.h>
#include <math.h>

#define NB    64
#define CCH   256
#define HW    2816     // 64*44 per channel
#define WW    44
#define PPX   176
#define TOPKK 22
#define TEMP_INV 8.0f
#define GATE_THR 0.05f
#define THREADS 352    // 11 warps: one per float4 column block
#define NUNITS 108     // 22 smap + 64 token + 22 pmap
#define NSTAGE 8
#define STCH   8       // channels per stage
#define NITER  (CCH/STCH)   // 32
#define XR     180     // padded channel stride within slot
#define SLOTF  (STCH*XR)

#define TOK_ELEMS   (NB*CCH*64)
#define PRES_ELEMS  (NB*64)
#define MAP_ELEMS   (NB*64*44*64)

typedef unsigned long long u64;

__device__ int g_cnt[NB];   // zero-init; self-resetting each launch

struct __align__(16) SM {
    float lbn8[CCH*8];      // normalized basis, k-duplicated pairs {x,x,y,y,z,z,w,w}
    float dotp[PPX*4];      // raw pooled projections [p][k]
    float sup[PPX*4];
    float pw[PPX*4];
    float pwT[4*PPX];
    float fe[PPX];
    float nrm[PPX];
    float red[32];
    float scal[16];
    int   ctr;
    int   flag;
};

#define SMEM_TOTAL ((int)(sizeof(SM) + NSTAGE*SLOTF*sizeof(float)))

__device__ __forceinline__ float wsum(float v) {
#pragma unroll
    for (int o = 16; o; o >>= 1) v += __shfl_xor_sync(0xffffffffu, v, o);
    return v;
}
__device__ __forceinline__ float wmaxr(float v) {
#pragma unroll
    for (int o = 16; o; o >>= 1) v = fmaxf(v, __shfl_xor_sync(0xffffffffu, v, o));
    return v;
}
__device__ __forceinline__ u64 pk2(float lo, float hi) {
    u64 r; asm("mov.b64 %0,{%1,%2};" : "=l"(r) : "f"(lo), "f"(hi)); return r;
}
__device__ __forceinline__ void up2(u64 v, float& a, float& b) {
    asm("mov.b64 {%0,%1},%2;" : "=f"(a), "=f"(b) : "l"(v));
}
__device__ __forceinline__ u64 ffma2(u64 a, u64 b, u64 c) {
    u64 d; asm("fma.rn.f32x2 %0,%1,%2,%3;" : "=l"(d) : "l"(a), "l"(b), "l"(c)); return d;
}
__device__ __forceinline__ u64 fadd2(u64 a, u64 b) {
    u64 d; asm("add.rn.f32x2 %0,%1,%2;" : "=l"(d) : "l"(a), "l"(b)); return d;
}
__device__ __forceinline__ void fill_stage(float* slot, const float* xb, int c0, int tid) {
    int ch = tid / 44, q = tid - 44 * ch;        // tid < 352 exactly covers 8ch x 44 float4
    const float* src = xb + (size_t)(c0 + ch) * HW + q * 4;
    unsigned daddr = (unsigned)__cvta_generic_to_shared(slot + ch * XR + q * 4);
    asm volatile("cp.async.cg.shared.global [%0],[%1],16;" :: "r"(daddr), "l"(src));
}

__global__ void __launch_bounds__(THREADS, 3)
fused_stripe_kernel(const float* __restrict__ x, const float* __restrict__ lb,
                    float* __restrict__ out_tok, float* __restrict__ out_pres,
                    float* __restrict__ out_smap, float* __restrict__ out_pmap)
{
    extern __shared__ char smraw[];
    SM& s = *reinterpret_cast<SM*>(smraw);
    float* ring = reinterpret_cast<float*>(smraw + sizeof(SM));
    const unsigned FULL = 0xffffffffu;
    const int tid = threadIdx.x, lane = tid & 31, wid = tid >> 5;
    const int blk = blockIdx.x;
    const int n = blk >> 4, g = blk & 15;
    const float* xb = x + (size_t)n * (CCH * HW) + (size_t)g * PPX;

    // ---------- Prologue: kick off first 7 stage fills ----------
#pragma unroll
    for (int ss = 0; ss < 7; ++ss) {
        fill_stage(ring + ss * SLOTF, xb, ss * STCH, tid);
        asm volatile("cp.async.commit_group;");
    }

    // ---------- Phase 1: load + L2-normalize latent basis ----------
    {
        if (tid == 0) { s.ctr = 0; s.flag = 0; }
        float v0 = 0, v1 = 0, v2 = 0, v3 = 0;
        if (tid < 256) {
            const float* lbg = lb + (size_t)g * (4 * CCH);
            v0 = lbg[tid]; v1 = lbg[CCH + tid]; v2 = lbg[2 * CCH + tid]; v3 = lbg[3 * CCH + tid];
            float s0 = wsum(v0 * v0), s1 = wsum(v1 * v1), s2 = wsum(v2 * v2), s3 = wsum(v3 * v3);
            if (lane == 0) { s.red[wid] = s0; s.red[8 + wid] = s1; s.red[16 + wid] = s2; s.red[24 + wid] = s3; }
        }
        __syncthreads();
        if (tid < 4) {
            float ss = 0.f;
#pragma unroll
            for (int j = 0; j < 8; ++j) ss += s.red[tid * 8 + j];
            s.scal[tid] = 1.0f / fmaxf(sqrtf(ss), 1e-12f);
        }
        __syncthreads();
        if (tid < 256) {
            float ox = v0 * s.scal[0], oy = v1 * s.scal[1], oz = v2 * s.scal[2], ow = v3 * s.scal[3];
            *reinterpret_cast<float4*>(&s.lbn8[tid * 8 + 0]) = make_float4(ox, ox, oy, oy);
            *reinterpret_cast<float4*>(&s.lbn8[tid * 8 + 4]) = make_float4(oz, oz, ow, ow);
        }
    }

    // ---------- Phase 2: (channel x row) lanes, horizontal-first stencil (8 shfl/iter) ----------
    {
        const int w = wid;                 // colblock 0..10
        const int c8 = lane >> 2, r = lane & 3;
        const float cb = (r == 1 || r == 2) ? 1.f : 0.f;   // xor3 neighbor valid only mid-rows
        const bool haslw = (w > 0), hasrw = (w < 10);
        const int xoff = c8 * XR + r * WW + w * 4;

        u64 pd0a = 0, pd0b = 0, pd1a = 0, pd1b = 0, pd2a = 0, pd2b = 0, pd3a = 0, pd3b = 0;
        u64 fea = 0, feb = 0, nra = 0, nrb = 0;

#pragma unroll 1
        for (int it = 0; it < NITER; ++it) {
            asm volatile("cp.async.wait_group 6;");
            __syncthreads();
            if (it + 7 < NITER)
                fill_stage(ring + ((it + 7) & (NSTAGE - 1)) * SLOTF, xb, (it + 7) * STCH, tid);
            asm volatile("cp.async.commit_group;");

            const float* st = ring + (it & (NSTAGE - 1)) * SLOTF;
            ulonglong2 xm = *reinterpret_cast<const ulonglong2*>(st + xoff);
            float ml = haslw ? st[xoff - 1] : 0.f;
            float mr = hasrw ? st[xoff + 4] : 0.f;

            float m0, m1, m2, m3;
            up2(xm.x, m0, m1); up2(xm.y, m2, m3);
            // horizontal 3-tap first (halo consumed in-registers)
            float t01 = m0 + m1, t23 = m2 + m3;
            float h0 = ml + t01, h1 = t01 + m2, h2 = m1 + t23, h3 = t23 + mr;
            // vertical 3-tap via xor1 (always valid neighbor) + xor3 (mid-rows only)
            float p0 = h0 + __shfl_xor_sync(FULL, h0, 1) + cb * __shfl_xor_sync(FULL, h0, 3);
            float p1 = h1 + __shfl_xor_sync(FULL, h1, 1) + cb * __shfl_xor_sync(FULL, h1, 3);
            float p2 = h2 + __shfl_xor_sync(FULL, h2, 1) + cb * __shfl_xor_sync(FULL, h2, 3);
            float p3 = h3 + __shfl_xor_sync(FULL, h3, 1) + cb * __shfl_xor_sync(FULL, h3, 3);

            u64 pl01 = pk2(p0, p1);
            u64 pl23 = pk2(p2, p3);

            const ulonglong2* lb8 = reinterpret_cast<const ulonglong2*>(&s.lbn8[(it * STCH + c8) * 8]);
            ulonglong2 lxy = lb8[0], lzw = lb8[1];
            pd0a = ffma2(pl01, lxy.x, pd0a); pd0b = ffma2(pl23, lxy.x, pd0b);
            pd1a = ffma2(pl01, lxy.y, pd1a); pd1b = ffma2(pl23, lxy.y, pd1b);
            pd2a = ffma2(pl01, lzw.x, pd2a); pd2b = ffma2(pl23, lzw.x, pd2b);
            pd3a = ffma2(pl01, lzw.y, pd3a); pd3b = ffma2(pl23, lzw.y, pd3b);
            fea = ffma2(xm.x, xm.x, fea);    feb = ffma2(xm.y, xm.y, feb);
            nra = ffma2(pl01, pl01, nra);    nrb = ffma2(pl23, pl23, nrb);
        }

        // cross-c8 reduction (lanes with equal r, strides 4/8/16)
#pragma unroll
        for (int off = 4; off <= 16; off <<= 1) {
            pd0a = fadd2(pd0a, __shfl_xor_sync(FULL, pd0a, off));
            pd0b = fadd2(pd0b, __shfl_xor_sync(FULL, pd0b, off));
            pd1a = fadd2(pd1a, __shfl_xor_sync(FULL, pd1a, off));
            pd1b = fadd2(pd1b, __shfl_xor_sync(FULL, pd1b, off));
            pd2a = fadd2(pd2a, __shfl_xor_sync(FULL, pd2a, off));
            pd2b = fadd2(pd2b, __shfl_xor_sync(FULL, pd2b, off));
            pd3a = fadd2(pd3a, __shfl_xor_sync(FULL, pd3a, off));
            pd3b = fadd2(pd3b, __shfl_xor_sync(FULL, pd3b, off));
            fea  = fadd2(fea,  __shfl_xor_sync(FULL, fea,  off));
            feb  = fadd2(feb,  __shfl_xor_sync(FULL, feb,  off));
            nra  = fadd2(nra,  __shfl_xor_sync(FULL, nra,  off));
            nrb  = fadd2(nrb,  __shfl_xor_sync(FULL, nrb,  off));
        }
        if (lane < 4) {
            const int po = lane * WW + w * 4;    // 4-aligned (44 % 4 == 0)
            float k0p0,k0p1,k0p2,k0p3, k1p0,k1p1,k1p2,k1p3;
            float k2p0,k2p1,k2p2,k2p3, k3p0,k3p1,k3p2,k3p3;
            up2(pd0a,k0p0,k0p1); up2(pd0b,k0p2,k0p3);
            up2(pd1a,k1p0,k1p1); up2(pd1b,k1p2,k1p3);
            up2(pd2a,k2p0,k2p1); up2(pd2b,k2p2,k2p3);
            up2(pd3a,k3p0,k3p1); up2(pd3b,k3p2,k3p3);
            float f0,f1,f2,f3, n0,n1,n2,n3;
            up2(fea,f0,f1); up2(feb,f2,f3);
            up2(nra,n0,n1); up2(nrb,n2,n3);
            *reinterpret_cast<float4*>(&s.dotp[(po+0)*4]) = make_float4(k0p0,k1p0,k2p0,k3p0);
            *reinterpret_cast<float4*>(&s.dotp[(po+1)*4]) = make_float4(k0p1,k1p1,k2p1,k3p1);
            *reinterpret_cast<float4*>(&s.dotp[(po+2)*4]) = make_float4(k0p2,k1p2,k2p2,k3p2);
            *reinterpret_cast<float4*>(&s.dotp[(po+3)*4]) = make_float4(k0p3,k1p3,k2p3,k3p3);
            *reinterpret_cast<float4*>(&s.fe[po])  = make_float4(f0*(1.f/CCH), f1*(1.f/CCH),
                                                                 f2*(1.f/CCH), f3*(1.f/CCH));
            *reinterpret_cast<float4*>(&s.nrm[po]) = make_float4(n0, n1, n2, n3);
        }
    }
    __syncthreads();

    // ---------- Phase 3: fe max + active count ----------
    float fev = 0.f, nmv = 0.f;
    float4 dtv = make_float4(0.f, 0.f, 0.f, 0.f);
    if (tid < PPX) {
        fev = s.fe[tid]; nmv = s.nrm[tid];
        dtv = *reinterpret_cast<float4*>(&s.dotp[tid * 4]);
    }
    {
        float m = wmaxr((tid < PPX) ? fev : 0.f);
        if (lane == 0) s.red[wid] = m;
    }
    __syncthreads();
    float invmax;
    {
        float mm = s.red[0];
#pragma unroll
        for (int j = 1; j < 11; ++j) mm = fmaxf(mm, s.red[j]);
        invmax = 1.0f / fmaxf(mm, 1e-6f);
    }
    int pred = (tid < PPX) && (fev * invmax > GATE_THR);
    int cnt = __syncthreads_count(pred);

    // ---------- Phase 4: softmax routing -> support (1/9 & 1/81 cancel) ----------
    if (tid < PPX) {
        float sc = TEMP_INV / fmaxf(sqrtf(nmv), 9e-12f);
        float l0 = dtv.x * sc, l1 = dtv.y * sc, l2 = dtv.z * sc, l3 = dtv.w * sc;
        float m = fmaxf(fmaxf(l0, l1), fmaxf(l2, l3));
        float e0 = __expf(l0 - m), e1 = __expf(l1 - m), e2 = __expf(l2 - m), e3 = __expf(l3 - m);
        float inv = 1.0f / (e0 + e1 + e2 + e3);
        float fes = fev * invmax;
        float act = (cnt > 0) ? (fes > GATE_THR ? 1.f : 0.f) : (fes > 0.f ? 1.f : 0.f);
        float w_ = inv * act;
        *reinterpret_cast<float4*>(&s.sup[tid * 4]) = make_float4(e0 * w_, e1 * w_, e2 * w_, e3 * w_);
    }
    __syncthreads();

    // ---------- Phase 5: overlapped tail ----------
    float* smb = out_smap + (size_t)n * (HW * 64) + (size_t)g * (PPX * 64);
    float* pmb = out_pmap + (size_t)n * (HW * 64) + (size_t)g * (PPX * 64);

    if (wid == 0) {
        float s0 = 0, s1 = 0, s2 = 0, s3 = 0;
        for (int pp = lane; pp < PPX; pp += 32) {
            float4 v = *reinterpret_cast<float4*>(&s.sup[pp * 4]);
            s0 += v.x; s1 += v.y; s2 += v.z; s3 += v.w;
        }
        s0 = wsum(s0); s1 = wsum(s1); s2 = wsum(s2); s3 = wsum(s3);
        float i0 = 1.0f / fmaxf(s0, 1e-6f), i1 = 1.0f / fmaxf(s1, 1e-6f);
        float i2 = 1.0f / fmaxf(s2, 1e-6f), i3 = 1.0f / fmaxf(s3, 1e-6f);
        for (int pp = lane; pp < PPX; pp += 32) {
            float4 v = *reinterpret_cast<float4*>(&s.sup[pp * 4]);
            float4 w = make_float4(v.x * i0, v.y * i1, v.z * i2, v.w * i3);
            *reinterpret_cast<float4*>(&s.pw[pp * 4]) = w;
            s.pwT[0 * PPX + pp] = w.x;
            s.pwT[1 * PPX + pp] = w.y;
            s.pwT[2 * PPX + pp] = w.z;
            s.pwT[3 * PPX + pp] = w.w;
        }
        __threadfence_block();
        if (lane == 0) s.flag = 1;
    } else if (wid >= 4 && wid < 8) {
        const int k = wid - 4;
        float v[6];
#pragma unroll
        for (int j = 0; j < 6; ++j) {
            int pp = lane + 32 * j;
            v[j] = (pp < PPX) ? s.sup[pp * 4 + k] : -1.0f;
        }
        float sum = 0.f;
        for (int it = 0; it < TOPKK; ++it) {
            float lm = v[0]; int li = 0;
#pragma unroll
            for (int j = 1; j < 6; ++j) { if (v[j] > lm) { lm = v[j]; li = j; } }
            float wm = wmaxr(lm);
            unsigned msk = __ballot_sync(FULL, lm == wm);
            int src = __ffs(msk) - 1;
            if (lane == src) v[li] = -1.0f;
            sum += wm;
        }
        if (lane == 0) {
            out_pres[n * 64 + g * 4 + k] = sum * (1.0f / TOPKK);
            __threadfence();
        }
    }

    // work queue: units [0,22)=smap, [22,86)=tokens, [86,108)=pmap
    {
        const float4 z4 = make_float4(0.f, 0.f, 0.f, 0.f);
        bool pwReady = false;
        for (;;) {
            int u;
            if (lane == 0) u = atomicAdd(&s.ctr, 1);
            u = __shfl_sync(FULL, u, 0);
            if (u >= NUNITS) break;
            if (u >= 22 && !pwReady) {
                while (*((volatile int*)&s.flag) == 0) {}
                __threadfence_block();
                pwReady = true;
            }
            if (u < 22) {
                int base = u * 128;
#pragma unroll
                for (int j = 0; j < 4; ++j) {
                    int idx = base + j * 32 + lane;
                    int pp = idx >> 4, qd = idx & 15;
                    float4 sv = (qd == g) ? *reinterpret_cast<float4*>(&s.sup[pp * 4]) : z4;
                    *reinterpret_cast<float4*>(smb + (size_t)idx * 4) = sv;
                }
            } else if (u < 86) {
                const int grp = lane >> 3, gl = lane & 7;
                const int c = (u - 22) * 4 + grp;
                const float* xc = xb + (size_t)c * HW;
                u64 a0 = 0, a1 = 0, a2 = 0, a3 = 0;
#pragma unroll
                for (int it = 0; it < 6; ++it) {
                    int p0 = it * 32 + gl * 4;
                    if (p0 < PPX) {
                        ulonglong2 xv = *reinterpret_cast<const ulonglong2*>(xc + p0);
                        ulonglong2 w0 = *reinterpret_cast<const ulonglong2*>(&s.pwT[0 * PPX + p0]);
                        ulonglong2 w1 = *reinterpret_cast<const ulonglong2*>(&s.pwT[1 * PPX + p0]);
                        ulonglong2 w2 = *reinterpret_cast<const ulonglong2*>(&s.pwT[2 * PPX + p0]);
                        ulonglong2 w3 = *reinterpret_cast<const ulonglong2*>(&s.pwT[3 * PPX + p0]);
                        a0 = ffma2(xv.y, w0.y, ffma2(xv.x, w0.x, a0));
                        a1 = ffma2(xv.y, w1.y, ffma2(xv.x, w1.x, a1));
                        a2 = ffma2(xv.y, w2.y, ffma2(xv.x, w2.x, a2));
                        a3 = ffma2(xv.y, w3.y, ffma2(xv.x, w3.x, a3));
                    }
                }
                float x0, y0, x1, y1, x2, y2, x3, y3;
                up2(a0, x0, y0); up2(a1, x1, y1); up2(a2, x2, y2); up2(a3, x3, y3);
                float f0 = x0 + y0, f1 = x1 + y1, f2 = x2 + y2, f3 = x3 + y3;
#pragma unroll
                for (int m = 1; m <= 4; m <<= 1) {
                    f0 += __shfl_xor_sync(FULL, f0, m);
                    f1 += __shfl_xor_sync(FULL, f1, m);
                    f2 += __shfl_xor_sync(FULL, f2, m);
                    f3 += __shfl_xor_sync(FULL, f3, m);
                }
                if (gl == 0)
                    *reinterpret_cast<float4*>(out_tok + ((size_t)(n * CCH + c) * 64 + g * 4)) =
                        make_float4(f0, f1, f2, f3);
            } else {
                int base = (u - 86) * 128;
#pragma unroll
                for (int j = 0; j < 4; ++j) {
                    int idx = base + j * 32 + lane;
                    int pp = idx >> 4, qd = idx & 15;
                    float4 pv = (qd == g) ? *reinterpret_cast<float4*>(&s.pw[pp * 4]) : z4;
                    *reinterpret_cast<float4*>(pmb + (size_t)idx * 4) = pv;
                }
            }
        }
    }

    // ---------- Phase 9: last CTA of batch n normalizes presence ----------
    __syncthreads();
    if (tid == 0) {
        __threadfence();
        int old = atomicAdd(&g_cnt[n], 1);
        s.red[0] = (old == 15) ? 1.f : 0.f;
    }
    __syncthreads();
    if (s.red[0] != 0.f && wid == 0) {
        __threadfence();
        float a = out_pres[n * 64 + lane];
        float b = out_pres[n * 64 + 32 + lane];
        float t = wsum(a + b);
        float inv = 1.0f / fmaxf(t, 1e-6f);
        out_pres[n * 64 + lane] = a * inv;
        out_pres[n * 64 + 32 + lane] = b * inv;
        if (lane == 0) g_cnt[n] = 0;
    }
}

extern "C" void kernel_launch(void* const* d_in, const int* in_sizes, int n_in,
                              void* d_out, int out_size)
{
    const float* x  = (const float*)d_in[0];
    const float* lb = (const float*)d_in[1];
    float* out = (float*)d_out;

    float* tok  = out;
    float* pres = out + TOK_ELEMS;
    float* smap = out + TOK_ELEMS + PRES_ELEMS;
    float* pmap = out + TOK_ELEMS + PRES_ELEMS + MAP_ELEMS;

    cudaFuncSetAttribute(fused_stripe_kernel,
                         cudaFuncAttributeMaxDynamicSharedMemorySize, SMEM_TOTAL);
    fused_stripe_kernel<<<NB * 16, THREADS, SMEM_TOTAL>>>(x, lb, tok, pres, smap, pmap);
}

// round 16
// speedup vs baseline: 1.7464x; 1.0045x over previous
#include <cuda_runtime.h>
#include <math.h>

#define NB    64
#define CCH   256
#define HW    2816     // 64*44 per channel
#define WW    44
#define PPX   176
#define TOPKK 22
#define TEMP_INV 8.0f
#define GATE_THR 0.05f
#define THREADS 352    // 11 warps: one per float4 column block
#define NUNITS 108     // 22 smap + 64 token + 22 pmap
#define NSTAGE 4
#define STCH   16      // channels per stage (two 8-channel halves)
#define NITER  (CCH/STCH)   // 16
#define XR     180     // padded channel stride within slot
#define SLOTF  (STCH*XR)

#define TOK_ELEMS   (NB*CCH*64)
#define PRES_ELEMS  (NB*64)
#define MAP_ELEMS   (NB*64*44*64)

typedef unsigned long long u64;

__device__ int g_cnt[NB];   // zero-init; self-resetting each launch

struct __align__(16) SM {
    float lbn8[CCH*8];      // normalized basis, k-duplicated pairs {x,x,y,y,z,z,w,w}
    float dotp[PPX*4];      // raw pooled projections [p][k]
    float sup[PPX*4];
    float pw[PPX*4];
    float pwT[4*PPX];
    float fe[PPX];
    float nrm[PPX];
    float red[32];
    float scal[16];
    int   ctr;
    int   flag;
};

#define SMEM_TOTAL ((int)(sizeof(SM) + NSTAGE*SLOTF*sizeof(float)))

__device__ __forceinline__ float wsum(float v) {
#pragma unroll
    for (int o = 16; o; o >>= 1) v += __shfl_xor_sync(0xffffffffu, v, o);
    return v;
}
__device__ __forceinline__ float wmaxr(float v) {
#pragma unroll
    for (int o = 16; o; o >>= 1) v = fmaxf(v, __shfl_xor_sync(0xffffffffu, v, o));
    return v;
}
__device__ __forceinline__ u64 pk2(float lo, float hi) {
    u64 r; asm("mov.b64 %0,{%1,%2};" : "=l"(r) : "f"(lo), "f"(hi)); return r;
}
__device__ __forceinline__ void up2(u64 v, float& a, float& b) {
    asm("mov.b64 {%0,%1},%2;" : "=f"(a), "=f"(b) : "l"(v));
}
__device__ __forceinline__ u64 ffma2(u64 a, u64 b, u64 c) {
    u64 d; asm("fma.rn.f32x2 %0,%1,%2,%3;" : "=l"(d) : "l"(a), "l"(b), "l"(c)); return d;
}
__device__ __forceinline__ u64 fadd2(u64 a, u64 b) {
    u64 d; asm("add.rn.f32x2 %0,%1,%2;" : "=l"(d) : "l"(a), "l"(b)); return d;
}
__device__ __forceinline__ void fill_stage(float* slot, const float* xb, int c0, int tid) {
#pragma unroll
    for (int h = 0; h < 2; ++h) {
        int idx = tid + h * THREADS;            // 704 float4 tiles = 16ch x 44
        int ch = idx / 44, q = idx - 44 * ch;
        const float* src = xb + (size_t)(c0 + ch) * HW + q * 4;
        unsigned daddr = (unsigned)__cvta_generic_to_shared(slot + ch * XR + q * 4);
        asm volatile("cp.async.cg.shared.global [%0],[%1],16;" :: "r"(daddr), "l"(src));
    }
}

__global__ void __launch_bounds__(THREADS, 3)
fused_stripe_kernel(const float* __restrict__ x, const float* __restrict__ lb,
                    float* __restrict__ out_tok, float* __restrict__ out_pres,
                    float* __restrict__ out_smap, float* __restrict__ out_pmap)
{
    extern __shared__ char smraw[];
    SM& s = *reinterpret_cast<SM*>(smraw);
    float* ring = reinterpret_cast<float*>(smraw + sizeof(SM));
    const unsigned FULL = 0xffffffffu;
    const int tid = threadIdx.x, lane = tid & 31, wid = tid >> 5;
    const int blk = blockIdx.x;
    const int n = blk >> 4, g = blk & 15;
    const float* xb = x + (size_t)n * (CCH * HW) + (size_t)g * PPX;

    // ---------- Prologue: kick off first 3 stage fills ----------
#pragma unroll
    for (int ss = 0; ss < 3; ++ss) {
        fill_stage(ring + ss * SLOTF, xb, ss * STCH, tid);
        asm volatile("cp.async.commit_group;");
    }

    // ---------- Phase 1: load + L2-normalize latent basis ----------
    {
        if (tid == 0) { s.ctr = 0; s.flag = 0; }
        float v0 = 0, v1 = 0, v2 = 0, v3 = 0;
        if (tid < 256) {
            const float* lbg = lb + (size_t)g * (4 * CCH);
            v0 = lbg[tid]; v1 = lbg[CCH + tid]; v2 = lbg[2 * CCH + tid]; v3 = lbg[3 * CCH + tid];
            float s0 = wsum(v0 * v0), s1 = wsum(v1 * v1), s2 = wsum(v2 * v2), s3 = wsum(v3 * v3);
            if (lane == 0) { s.red[wid] = s0; s.red[8 + wid] = s1; s.red[16 + wid] = s2; s.red[24 + wid] = s3; }
        }
        __syncthreads();
        if (tid < 4) {
            float ss = 0.f;
#pragma unroll
            for (int j = 0; j < 8; ++j) ss += s.red[tid * 8 + j];
            s.scal[tid] = 1.0f / fmaxf(sqrtf(ss), 1e-12f);
        }
        __syncthreads();
        if (tid < 256) {
            float ox = v0 * s.scal[0], oy = v1 * s.scal[1], oz = v2 * s.scal[2], ow = v3 * s.scal[3];
            *reinterpret_cast<float4*>(&s.lbn8[tid * 8 + 0]) = make_float4(ox, ox, oy, oy);
            *reinterpret_cast<float4*>(&s.lbn8[tid * 8 + 4]) = make_float4(oz, oz, ow, ow);
        }
    }

    // ---------- Phase 2: 16 ch/stage, horizontal-first stencil, 1 barrier per 16 ch ----------
    {
        const int w = wid;                 // colblock 0..10
        const int c8 = lane >> 2, r = lane & 3;
        const float cb = (r == 1 || r == 2) ? 1.f : 0.f;   // xor3 neighbor valid only mid-rows
        const bool haslw = (w > 0), hasrw = (w < 10);
        const int xoff = c8 * XR + r * WW + w * 4;

        u64 pd0a = 0, pd0b = 0, pd1a = 0, pd1b = 0, pd2a = 0, pd2b = 0, pd3a = 0, pd3b = 0;
        u64 fea = 0, feb = 0, nra = 0, nrb = 0;

#pragma unroll 1
        for (int it = 0; it < NITER; ++it) {
            asm volatile("cp.async.wait_group 2;");
            __syncthreads();
            if (it + 3 < NITER)
                fill_stage(ring + ((it + 3) & (NSTAGE - 1)) * SLOTF, xb, (it + 3) * STCH, tid);
            asm volatile("cp.async.commit_group;");

            const float* st = ring + (it & (NSTAGE - 1)) * SLOTF;
#pragma unroll
            for (int h = 0; h < 2; ++h) {
                const int xo = xoff + h * (8 * XR);
                ulonglong2 xm = *reinterpret_cast<const ulonglong2*>(st + xo);
                float ml = haslw ? st[xo - 1] : 0.f;
                float mr = hasrw ? st[xo + 4] : 0.f;

                float m0, m1, m2, m3;
                up2(xm.x, m0, m1); up2(xm.y, m2, m3);
                float t01 = m0 + m1, t23 = m2 + m3;
                float h0 = ml + t01, h1 = t01 + m2, h2 = m1 + t23, h3 = t23 + mr;
                float p0 = h0 + __shfl_xor_sync(FULL, h0, 1) + cb * __shfl_xor_sync(FULL, h0, 3);
                float p1 = h1 + __shfl_xor_sync(FULL, h1, 1) + cb * __shfl_xor_sync(FULL, h1, 3);
                float p2 = h2 + __shfl_xor_sync(FULL, h2, 1) + cb * __shfl_xor_sync(FULL, h2, 3);
                float p3 = h3 + __shfl_xor_sync(FULL, h3, 1) + cb * __shfl_xor_sync(FULL, h3, 3);

                u64 pl01 = pk2(p0, p1);
                u64 pl23 = pk2(p2, p3);

                const ulonglong2* lb8 =
                    reinterpret_cast<const ulonglong2*>(&s.lbn8[(it * STCH + h * 8 + c8) * 8]);
                ulonglong2 lxy = lb8[0], lzw = lb8[1];
                pd0a = ffma2(pl01, lxy.x, pd0a); pd0b = ffma2(pl23, lxy.x, pd0b);
                pd1a = ffma2(pl01, lxy.y, pd1a); pd1b = ffma2(pl23, lxy.y, pd1b);
                pd2a = ffma2(pl01, lzw.x, pd2a); pd2b = ffma2(pl23, lzw.x, pd2b);
                pd3a = ffma2(pl01, lzw.y, pd3a); pd3b = ffma2(pl23, lzw.y, pd3b);
                fea = ffma2(xm.x, xm.x, fea);    feb = ffma2(xm.y, xm.y, feb);
                nra = ffma2(pl01, pl01, nra);    nrb = ffma2(pl23, pl23, nrb);
            }
        }

        // cross-c8 reduction (lanes with equal r, strides 4/8/16)
#pragma unroll
        for (int off = 4; off <= 16; off <<= 1) {
            pd0a = fadd2(pd0a, __shfl_xor_sync(FULL, pd0a, off));
            pd0b = fadd2(pd0b, __shfl_xor_sync(FULL, pd0b, off));
            pd1a = fadd2(pd1a, __shfl_xor_sync(FULL, pd1a, off));
            pd1b = fadd2(pd1b, __shfl_xor_sync(FULL, pd1b, off));
            pd2a = fadd2(pd2a, __shfl_xor_sync(FULL, pd2a, off));
            pd2b = fadd2(pd2b, __shfl_xor_sync(FULL, pd2b, off));
            pd3a = fadd2(pd3a, __shfl_xor_sync(FULL, pd3a, off));
            pd3b = fadd2(pd3b, __shfl_xor_sync(FULL, pd3b, off));
            fea  = fadd2(fea,  __shfl_xor_sync(FULL, fea,  off));
            feb  = fadd2(feb,  __shfl_xor_sync(FULL, feb,  off));
            nra  = fadd2(nra,  __shfl_xor_sync(FULL, nra,  off));
            nrb  = fadd2(nrb,  __shfl_xor_sync(FULL, nrb,  off));
        }
        if (lane < 4) {
            const int po = lane * WW + w * 4;    // 4-aligned (44 % 4 == 0)
            float k0p0,k0p1,k0p2,k0p3, k1p0,k1p1,k1p2,k1p3;
            float k2p0,k2p1,k2p2,k2p3, k3p0,k3p1,k3p2,k3p3;
            up2(pd0a,k0p0,k0p1); up2(pd0b,k0p2,k0p3);
            up2(pd1a,k1p0,k1p1); up2(pd1b,k1p2,k1p3);
            up2(pd2a,k2p0,k2p1); up2(pd2b,k2p2,k2p3);
            up2(pd3a,k3p0,k3p1); up2(pd3b,k3p2,k3p3);
            float f0,f1,f2,f3, n0,n1,n2,n3;
            up2(fea,f0,f1); up2(feb,f2,f3);
            up2(nra,n0,n1); up2(nrb,n2,n3);
            *reinterpret_cast<float4*>(&s.dotp[(po+0)*4]) = make_float4(k0p0,k1p0,k2p0,k3p0);
            *reinterpret_cast<float4*>(&s.dotp[(po+1)*4]) = make_float4(k0p1,k1p1,k2p1,k3p1);
            *reinterpret_cast<float4*>(&s.dotp[(po+2)*4]) = make_float4(k0p2,k1p2,k2p2,k3p2);
            *reinterpret_cast<float4*>(&s.dotp[(po+3)*4]) = make_float4(k0p3,k1p3,k2p3,k3p3);
            *reinterpret_cast<float4*>(&s.fe[po])  = make_float4(f0*(1.f/CCH), f1*(1.f/CCH),
                                                                 f2*(1.f/CCH), f3*(1.f/CCH));
            *reinterpret_cast<float4*>(&s.nrm[po]) = make_float4(n0, n1, n2, n3);
        }
    }
    __syncthreads();

    // ---------- Phase 3: fe max + active count ----------
    float fev = 0.f, nmv = 0.f;
    float4 dtv = make_float4(0.f, 0.f, 0.f, 0.f);
    if (tid < PPX) {
        fev = s.fe[tid]; nmv = s.nrm[tid];
        dtv = *reinterpret_cast<float4*>(&s.dotp[tid * 4]);
    }
    {
        float m = wmaxr((tid < PPX) ? fev : 0.f);
        if (lane == 0) s.red[wid] = m;
    }
    __syncthreads();
    float invmax;
    {
        float mm = s.red[0];
#pragma unroll
        for (int j = 1; j < 11; ++j) mm = fmaxf(mm, s.red[j]);
        invmax = 1.0f / fmaxf(mm, 1e-6f);
    }
    int pred = (tid < PPX) && (fev * invmax > GATE_THR);
    int cnt = __syncthreads_count(pred);

    // ---------- Phase 4: softmax routing -> support (1/9 & 1/81 cancel) ----------
    if (tid < PPX) {
        float sc = TEMP_INV / fmaxf(sqrtf(nmv), 9e-12f);
        float l0 = dtv.x * sc, l1 = dtv.y * sc, l2 = dtv.z * sc, l3 = dtv.w * sc;
        float m = fmaxf(fmaxf(l0, l1), fmaxf(l2, l3));
        float e0 = __expf(l0 - m), e1 = __expf(l1 - m), e2 = __expf(l2 - m), e3 = __expf(l3 - m);
        float inv = 1.0f / (e0 + e1 + e2 + e3);
        float fes = fev * invmax;
        float act = (cnt > 0) ? (fes > GATE_THR ? 1.f : 0.f) : (fes > 0.f ? 1.f : 0.f);
        float w_ = inv * act;
        *reinterpret_cast<float4*>(&s.sup[tid * 4]) = make_float4(e0 * w_, e1 * w_, e2 * w_, e3 * w_);
    }
    __syncthreads();

    // ---------- Phase 5: overlapped tail ----------
    float* smb = out_smap + (size_t)n * (HW * 64) + (size_t)g * (PPX * 64);
    float* pmb = out_pmap + (size_t)n * (HW * 64) + (size_t)g * (PPX * 64);

    if (wid == 0) {
        float s0 = 0, s1 = 0, s2 = 0, s3 = 0;
        for (int pp = lane; pp < PPX; pp += 32) {
            float4 v = *reinterpret_cast<float4*>(&s.sup[pp * 4]);
            s0 += v.x; s1 += v.y; s2 += v.z; s3 += v.w;
        }
        s0 = wsum(s0); s1 = wsum(s1); s2 = wsum(s2); s3 = wsum(s3);
        float i0 = 1.0f / fmaxf(s0, 1e-6f), i1 = 1.0f / fmaxf(s1, 1e-6f);
        float i2 = 1.0f / fmaxf(s2, 1e-6f), i3 = 1.0f / fmaxf(s3, 1e-6f);
        for (int pp = lane; pp < PPX; pp += 32) {
            float4 v = *reinterpret_cast<float4*>(&s.sup[pp * 4]);
            float4 w = make_float4(v.x * i0, v.y * i1, v.z * i2, v.w * i3);
            *reinterpret_cast<float4*>(&s.pw[pp * 4]) = w;
            s.pwT[0 * PPX + pp] = w.x;
            s.pwT[1 * PPX + pp] = w.y;
            s.pwT[2 * PPX + pp] = w.z;
            s.pwT[3 * PPX + pp] = w.w;
        }
        __threadfence_block();
        if (lane == 0) s.flag = 1;
    } else if (wid >= 4 && wid < 8) {
        const int k = wid - 4;
        float v[6];
#pragma unroll
        for (int j = 0; j < 6; ++j) {
            int pp = lane + 32 * j;
            v[j] = (pp < PPX) ? s.sup[pp * 4 + k] : -1.0f;
        }
        float sum = 0.f;
        for (int it = 0; it < TOPKK; ++it) {
            float lm = v[0]; int li = 0;
#pragma unroll
            for (int j = 1; j < 6; ++j) { if (v[j] > lm) { lm = v[j]; li = j; } }
            float wm = wmaxr(lm);
            unsigned msk = __ballot_sync(FULL, lm == wm);
            int src = __ffs(msk) - 1;
            if (lane == src) v[li] = -1.0f;
            sum += wm;
        }
        if (lane == 0) {
            out_pres[n * 64 + g * 4 + k] = sum * (1.0f / TOPKK);
            __threadfence();
        }
    }

    // work queue: units [0,22)=smap, [22,86)=tokens, [86,108)=pmap
    {
        const float4 z4 = make_float4(0.f, 0.f, 0.f, 0.f);
        bool pwReady = false;
        for (;;) {
            int u;
            if (lane == 0) u = atomicAdd(&s.ctr, 1);
            u = __shfl_sync(FULL, u, 0);
            if (u >= NUNITS) break;
            if (u >= 22 && !pwReady) {
                while (*((volatile int*)&s.flag) == 0) {}
                __threadfence_block();
                pwReady = true;
            }
            if (u < 22) {
                int base = u * 128;
#pragma unroll
                for (int j = 0; j < 4; ++j) {
                    int idx = base + j * 32 + lane;
                    int pp = idx >> 4, qd = idx & 15;
                    float4 sv = (qd == g) ? *reinterpret_cast<float4*>(&s.sup[pp * 4]) : z4;
                    *reinterpret_cast<float4*>(smb + (size_t)idx * 4) = sv;
                }
            } else if (u < 86) {
                const int grp = lane >> 3, gl = lane & 7;
                const int c = (u - 22) * 4 + grp;
                const float* xc = xb + (size_t)c * HW;
                u64 a0 = 0, a1 = 0, a2 = 0, a3 = 0;
#pragma unroll
                for (int it = 0; it < 6; ++it) {
                    int p0 = it * 32 + gl * 4;
                    if (p0 < PPX) {
                        ulonglong2 xv = *reinterpret_cast<const ulonglong2*>(xc + p0);
                        ulonglong2 w0 = *reinterpret_cast<const ulonglong2*>(&s.pwT[0 * PPX + p0]);
                        ulonglong2 w1 = *reinterpret_cast<const ulonglong2*>(&s.pwT[1 * PPX + p0]);
                        ulonglong2 w2 = *reinterpret_cast<const ulonglong2*>(&s.pwT[2 * PPX + p0]);
                        ulonglong2 w3 = *reinterpret_cast<const ulonglong2*>(&s.pwT[3 * PPX + p0]);
                        a0 = ffma2(xv.y, w0.y, ffma2(xv.x, w0.x, a0));
                        a1 = ffma2(xv.y, w1.y, ffma2(xv.x, w1.x, a1));
                        a2 = ffma2(xv.y, w2.y, ffma2(xv.x, w2.x, a2));
                        a3 = ffma2(xv.y, w3.y, ffma2(xv.x, w3.x, a3));
                    }
                }
                float x0, y0, x1, y1, x2, y2, x3, y3;
                up2(a0, x0, y0); up2(a1, x1, y1); up2(a2, x2, y2); up2(a3, x3, y3);
                float f0 = x0 + y0, f1 = x1 + y1, f2 = x2 + y2, f3 = x3 + y3;
#pragma unroll
                for (int m = 1; m <= 4; m <<= 1) {
                    f0 += __shfl_xor_sync(FULL, f0, m);
                    f1 += __shfl_xor_sync(FULL, f1, m);
                    f2 += __shfl_xor_sync(FULL, f2, m);
                    f3 += __shfl_xor_sync(FULL, f3, m);
                }
                if (gl == 0)
                    *reinterpret_cast<float4*>(out_tok + ((size_t)(n * CCH + c) * 64 + g * 4)) =
                        make_float4(f0, f1, f2, f3);
            } else {
                int base = (u - 86) * 128;
#pragma unroll
                for (int j = 0; j < 4; ++j) {
                    int idx = base + j * 32 + lane;
                    int pp = idx >> 4, qd = idx & 15;
                    float4 pv = (qd == g) ? *reinterpret_cast<float4*>(&s.pw[pp * 4]) : z4;
                    *reinterpret_cast<float4*>(pmb + (size_t)idx * 4) = pv;
                }
            }
        }
    }

    // ---------- Phase 9: last CTA of batch n normalizes presence ----------
    __syncthreads();
    if (tid == 0) {
        __threadfence();
        int old = atomicAdd(&g_cnt[n], 1);
        s.red[0] = (old == 15) ? 1.f : 0.f;
    }
    __syncthreads();
    if (s.red[0] != 0.f && wid == 0) {
        __threadfence();
        float a = out_pres[n * 64 + lane];
        float b = out_pres[n * 64 + 32 + lane];
        float t = wsum(a + b);
        float inv = 1.0f / fmaxf(t, 1e-6f);
        out_pres[n * 64 + lane] = a * inv;
        out_pres[n * 64 + 32 + lane] = b * inv;
        if (lane == 0) g_cnt[n] = 0;
    }
}

extern "C" void kernel_launch(void* const* d_in, const int* in_sizes, int n_in,
                              void* d_out, int out_size)
{
    const float* x  = (const float*)d_in[0];
    const float* lb = (const float*)d_in[1];
    float* out = (float*)d_out;

    float* tok  = out;
    float* pres = out + TOK_ELEMS;
    float* smap = out + TOK_ELEMS + PRES_ELEMS;
    float* pmap = out + TOK_ELEMS + PRES_ELEMS + MAP_ELEMS;

    cudaFuncSetAttribute(fused_stripe_kernel,
                         cudaFuncAttributeMaxDynamicSharedMemorySize, SMEM_TOTAL);
    fused_stripe_kernel<<<NB * 16, THREADS, SMEM_TOTAL>>>(x, lb, tok, pres, smap, pmap);
}